// round 14
// baseline (speedup 1.0000x reference)
#include <cuda_runtime.h>
#include <cuda_fp16.h>
#include <cstdint>

#define BB 2
#define SS 2048
#define DD 2048
#define HH 8
#define DKK 256
#define SCALING 0.0625f
#define NEGV (-1e9f)
#define QSPAD 72      // BK=64 row stride (halves): 144B, ldsm conflict-free
#define QPAD 264      // score persistent-Q row stride (halves)

// Scratch (device globals; no allocation allowed)
__device__ __half g_xh[(size_t)BB * SS * DD];
__device__ __half g_Wh[3][(size_t)DD * DD];   // packed [3*DD][DD]
__device__ float  g_bias[3 * DD];
__device__ __half g_Qh[(size_t)BB * SS * DD];
__device__ __half g_Kh[(size_t)BB * SS * DD];
__device__ __half g_Vh[(size_t)BB * SS * DD];
__device__ float  g_score[BB * HH * SS];
__device__ float  g_pool[BB * DD];

// ---------------------------------------------------------------------------
// helpers
// ---------------------------------------------------------------------------
#define MMA_F16(d0,d1,d2,d3,a0,a1,a2,a3,b0,b1)                                \
    asm volatile("mma.sync.aligned.m16n8k16.row.col.f32.f16.f16.f32 "         \
                 "{%0,%1,%2,%3},{%4,%5,%6,%7},{%8,%9},{%0,%1,%2,%3};"         \
                 : "+f"(d0), "+f"(d1), "+f"(d2), "+f"(d3)                     \
                 : "r"(a0), "r"(a1), "r"(a2), "r"(a3), "r"(b0), "r"(b1))

#define LDSM_X4(r0,r1,r2,r3,addr)                                             \
    asm volatile("ldmatrix.sync.aligned.m8n8.x4.shared.b16 {%0,%1,%2,%3},[%4];" \
                 : "=r"(r0), "=r"(r1), "=r"(r2), "=r"(r3) : "r"(addr))

__device__ __forceinline__ void cp16(void* smem, const void* gmem) {
    uint32_t sa = (uint32_t)__cvta_generic_to_shared(smem);
    asm volatile("cp.async.cg.shared.global [%0], [%1], 16;" :: "r"(sa), "l"(gmem));
}
__device__ __forceinline__ void cp_commit() { asm volatile("cp.async.commit_group;"); }
template<int N> __device__ __forceinline__ void cp_wait() {
    asm volatile("cp.async.wait_group %0;" :: "n"(N));
}
__device__ __forceinline__ uint32_t s2u(const void* p) {
    return (uint32_t)__cvta_generic_to_shared(p);
}

// ---------------------------------------------------------------------------
// Fused f32->f16 convert of x + Wq/Wk/Wv
// ---------------------------------------------------------------------------
#define NX4 (1 << 22)
#define NW4 (1 << 20)

__global__ void __launch_bounds__(256) f2h_all_kernel(
    const float* __restrict__ x,
    const float* __restrict__ w0, const float* __restrict__ w1,
    const float* __restrict__ w2,
    __half* __restrict__ xh, __half* __restrict__ wh)
{
    int i = blockIdx.x * blockDim.x + threadIdx.x;
    const float* in;
    __half* out;
    int off;
    if (i < NX4) {
        in = x; out = xh; off = i;
    } else {
        int j = i - NX4;
        int seg = j >> 20;
        off = j & (NW4 - 1);
        in = (seg == 0) ? w0 : (seg == 1) ? w1 : w2;
        out = wh + (size_t)seg * DD * DD;
    }
    float4 v = reinterpret_cast<const float4*>(in)[off];
    reinterpret_cast<__half2*>(out)[2 * off] = __floats2half2_rn(v.x, v.y);
    reinterpret_cast<__half2*>(out)[2 * off + 1] = __floats2half2_rn(v.z, v.w);
}

// pack biases AND zero the pool accumulator (one launch)
__global__ void pack_bias_kernel(const float* __restrict__ b0,
                                 const float* __restrict__ b1,
                                 const float* __restrict__ b2,
                                 float* __restrict__ out,
                                 float* __restrict__ pool)
{
    int i = blockIdx.x * blockDim.x + threadIdx.x;
    if (i < DD) out[i] = b0[i];
    else if (i < 2 * DD) out[i] = b1[i - DD];
    else if (i < 3 * DD) out[i] = b2[i - 2 * DD];
    if (i < BB * DD) pool[i] = 0.f;
}

// ---------------------------------------------------------------------------
// Fused QKV fp16 NT GEMM (R13, unchanged). CTA 128x128, BK=64, 3-stage,
// 256 threads = 8 warps (2 x 4), warp tile 64x32, 2 CTA/SM.
// ---------------------------------------------------------------------------
#define QKV_SMEM (3 * 2 * 128 * QSPAD * 2)   // 110592 bytes

__global__ void __launch_bounds__(256) gemm_qkv_fused(
    const __half* __restrict__ A, const __half* __restrict__ W,
    const float* __restrict__ bias,
    __half* __restrict__ Qo, __half* __restrict__ Ko, __half* __restrict__ Vo)
{
    extern __shared__ __half smem[];
    __half (*As)[128][QSPAD] = reinterpret_cast<__half(*)[128][QSPAD]>(smem);
    __half (*Bs)[128][QSPAD] = reinterpret_cast<__half(*)[128][QSPAD]>(smem + 3 * 128 * QSPAD);

    const int K = DD;
    const int bm = blockIdx.y * 128;
    const int bn = blockIdx.x * 128;
    const int tid = threadIdx.x;
    const int warp = tid >> 5, lane = tid & 31;
    const int wm = warp & 1, wn = warp >> 1;
    const int g = lane >> 2, c = lane & 3;
    const int lrow = tid >> 3, lc8 = (tid & 7) * 8;

    float acc[4][4][4];
#pragma unroll
    for (int i = 0; i < 4; i++)
#pragma unroll
        for (int j = 0; j < 4; j++)
#pragma unroll
            for (int r = 0; r < 4; r++) acc[i][j][r] = 0.f;

    const int nk = K >> 6;   // 32

#pragma unroll
    for (int s = 0; s < 2; s++) {
        const int k0 = s << 6;
#pragma unroll
        for (int r = 0; r < 128; r += 32) {
            cp16(&As[s][lrow + r][lc8], A + (size_t)(bm + lrow + r) * K + k0 + lc8);
            cp16(&Bs[s][lrow + r][lc8], W + (size_t)(bn + lrow + r) * K + k0 + lc8);
        }
        cp_commit();
    }

    const int a_row = wm * 64 + (lane & 15);
    const int a_koff = (lane >> 4) << 3;
    const int b_row = wn * 32 + (lane & 7) + ((lane >> 4) << 3);
    const int b_koff = ((lane >> 3) & 1) << 3;

    for (int kt = 0; kt < nk; kt++) {
        cp_wait<1>();
        __syncthreads();

        const int pf = kt + 2;
        if (pf < nk) {
            const int pb = pf % 3;
            const int k0 = pf << 6;
#pragma unroll
            for (int r = 0; r < 128; r += 32) {
                cp16(&As[pb][lrow + r][lc8], A + (size_t)(bm + lrow + r) * K + k0 + lc8);
                cp16(&Bs[pb][lrow + r][lc8], W + (size_t)(bn + lrow + r) * K + k0 + lc8);
            }
        }
        cp_commit();

        const int buf = kt % 3;
#pragma unroll
        for (int kk = 0; kk < 4; kk++) {
            const int k = kk * 16;
            uint32_t af[4][4], bf[4][2];
#pragma unroll
            for (int mt = 0; mt < 4; mt++) {
                uint32_t ad = s2u(&As[buf][a_row + mt * 16][k + a_koff]);
                LDSM_X4(af[mt][0], af[mt][1], af[mt][2], af[mt][3], ad);
            }
#pragma unroll
            for (int nt2 = 0; nt2 < 2; nt2++) {
                uint32_t bd = s2u(&Bs[buf][b_row + nt2 * 16][k + b_koff]);
                LDSM_X4(bf[nt2 * 2][0], bf[nt2 * 2][1],
                        bf[nt2 * 2 + 1][0], bf[nt2 * 2 + 1][1], bd);
            }
#pragma unroll
            for (int mt = 0; mt < 4; mt++)
#pragma unroll
                for (int nt = 0; nt < 4; nt++)
                    MMA_F16(acc[mt][nt][0], acc[mt][nt][1], acc[mt][nt][2], acc[mt][nt][3],
                            af[mt][0], af[mt][1], af[mt][2], af[mt][3],
                            bf[nt][0], bf[nt][1]);
        }
    }

    const int seg = bn >> 11;                    // 0=Q 1=K 2=V
    const int nbase = bn & 2047;
    __half* dst = (seg == 0) ? Qo : (seg == 1) ? Ko : Vo;
#pragma unroll
    for (int mt = 0; mt < 4; mt++) {
        const int r = bm + wm * 64 + mt * 16 + g;
#pragma unroll
        for (int nt = 0; nt < 4; nt++) {
            const int gcol = bn + wn * 32 + nt * 8 + 2 * c;
            const int col = nbase + wn * 32 + nt * 8 + 2 * c;
            const float b0 = bias[gcol], b1 = bias[gcol + 1];
            *reinterpret_cast<__half2*>(&dst[(size_t)r * DD + col]) =
                __floats2half2_rn(acc[mt][nt][0] + b0, acc[mt][nt][1] + b1);
            *reinterpret_cast<__half2*>(&dst[(size_t)(r + 8) * DD + col]) =
                __floats2half2_rn(acc[mt][nt][2] + b0, acc[mt][nt][3] + b1);
        }
    }
}

// ---------------------------------------------------------------------------
// fp16 score kernel v2: 64-row i-tile (2 CTA/SM, finer waves), Q resident,
// K streamed with BK=64 (half the barriers). 8 warps = 2 wm(32 rows) x 4 wn.
// score[b,h,i] = SCALING*(sum_j leaky(q_i.k_j)*Wa[j] + ba)
// ---------------------------------------------------------------------------
#define SC_OFF_K (64 * QPAD)                          // halves
#define SC_OFF_RED (SC_OFF_K + 3 * 128 * QSPAD)       // halves
#define SC_SMEM_BYTES ((SC_OFF_RED) * 2 + 4 * 64 * 4)

__global__ void __launch_bounds__(256) score_f16_kernel(
    const __half* __restrict__ Q, const __half* __restrict__ Kb,
    const float* __restrict__ Wa, const float* __restrict__ ba,
    float* __restrict__ score)
{
    extern __shared__ __half hsmem[];
    __half (*Qs)[QPAD] = reinterpret_cast<__half(*)[QPAD]>(hsmem);
    __half (*Ks)[128][QSPAD] = reinterpret_cast<__half(*)[128][QSPAD]>(hsmem + SC_OFF_K);
    float (*red)[64] = reinterpret_cast<float(*)[64]>(hsmem + SC_OFF_RED);

    const int b = blockIdx.z, h = blockIdx.y;
    const int i0 = blockIdx.x * 64;
    const __half* Qg = Q + (size_t)b * SS * DD + (size_t)h * DKK;
    const __half* Kg = Kb + (size_t)b * SS * DD + (size_t)h * DKK;

    const int tid = threadIdx.x;
    const int warp = tid >> 5, lane = tid & 31;
    const int wm = warp & 1, wn = warp >> 1;
    const int g = lane >> 2, c = lane & 3;
    const int lrow = tid >> 3, lc8 = (tid & 7) * 8;   // K loader: 8 chunks/row

    const int a_row = wm * 32 + (lane & 15);
    const int a_koff = (lane >> 4) << 3;
    const int b_row = wn * 32 + (lane & 7) + ((lane >> 4) << 3);
    const int b_koff = ((lane >> 3) & 1) << 3;

    // one-time Q tile load: 64 rows x 256 halves = 2048 16B chunks
#pragma unroll
    for (int t = 0; t < 8; t++) {
        int chunk = tid + t * 256;
        int row = chunk >> 5, cc = chunk & 31;
        cp16(&Qs[row][cc * 8], Qg + (size_t)(i0 + row) * DD + cc * 8);
    }
    cp_commit();

    float racc[2][2];
#pragma unroll
    for (int mt = 0; mt < 2; mt++) { racc[mt][0] = 0.f; racc[mt][1] = 0.f; }

    const int nk = DKK >> 6;   // 4

    for (int j0 = 0; j0 < SS; j0 += 128) {
        float acc[2][4][4];
#pragma unroll
        for (int i = 0; i < 2; i++)
#pragma unroll
            for (int j = 0; j < 4; j++)
#pragma unroll
                for (int r = 0; r < 4; r++) acc[i][j][r] = 0.f;

#pragma unroll
        for (int s = 0; s < 2; s++) {
            const int k0 = s << 6;
#pragma unroll
            for (int r = 0; r < 128; r += 32)
                cp16(&Ks[s][lrow + r][lc8], Kg + (size_t)(j0 + lrow + r) * DD + k0 + lc8);
            cp_commit();
        }

        for (int kt = 0; kt < nk; kt++) {
            cp_wait<1>();
            __syncthreads();

            const int pf = kt + 2;
            if (pf < nk) {
                const int pb = pf % 3;
                const int k0 = pf << 6;
#pragma unroll
                for (int r = 0; r < 128; r += 32)
                    cp16(&Ks[pb][lrow + r][lc8], Kg + (size_t)(j0 + lrow + r) * DD + k0 + lc8);
            }
            cp_commit();

            const int buf = kt % 3;
            const int kg = kt << 6;      // Q's global k offset
#pragma unroll
            for (int kk = 0; kk < 4; kk++) {
                const int k = kk * 16;
                uint32_t af[2][4], bf[4][2];
#pragma unroll
                for (int mt = 0; mt < 2; mt++) {
                    uint32_t ad = s2u(&Qs[a_row + mt * 16][kg + k + a_koff]);
                    LDSM_X4(af[mt][0], af[mt][1], af[mt][2], af[mt][3], ad);
                }
#pragma unroll
                for (int nt2 = 0; nt2 < 2; nt2++) {
                    uint32_t bd = s2u(&Ks[buf][b_row + nt2 * 16][k + b_koff]);
                    LDSM_X4(bf[nt2 * 2][0], bf[nt2 * 2][1],
                            bf[nt2 * 2 + 1][0], bf[nt2 * 2 + 1][1], bd);
                }
#pragma unroll
                for (int mt = 0; mt < 2; mt++)
#pragma unroll
                    for (int nt = 0; nt < 4; nt++)
                        MMA_F16(acc[mt][nt][0], acc[mt][nt][1], acc[mt][nt][2], acc[mt][nt][3],
                                af[mt][0], af[mt][1], af[mt][2], af[mt][3],
                                bf[nt][0], bf[nt][1]);
            }
        }
        __syncthreads();   // protect K stages from next j-tile prefetch

        // fused epilogue: leaky_relu -> * Wa[j] -> fold into per-row accumulator
#pragma unroll
        for (int nt = 0; nt < 4; nt++) {
            const int colg = j0 + wn * 32 + nt * 8 + 2 * c;
            const float wa0 = Wa[colg], wa1 = Wa[colg + 1];
#pragma unroll
            for (int mt = 0; mt < 2; mt++) {
                float e0 = acc[mt][nt][0]; e0 = (e0 >= 0.f) ? e0 : 0.1f * e0;
                float e1 = acc[mt][nt][1]; e1 = (e1 >= 0.f) ? e1 : 0.1f * e1;
                float e2 = acc[mt][nt][2]; e2 = (e2 >= 0.f) ? e2 : 0.1f * e2;
                float e3 = acc[mt][nt][3]; e3 = (e3 >= 0.f) ? e3 : 0.1f * e3;
                racc[mt][0] += e0 * wa0 + e1 * wa1;
                racc[mt][1] += e2 * wa0 + e3 * wa1;
            }
        }
    }

    // reduce across the 4 "c" lanes of each quad
#pragma unroll
    for (int mt = 0; mt < 2; mt++) {
#pragma unroll
        for (int hf = 0; hf < 2; hf++) {
            float v = racc[mt][hf];
            v += __shfl_xor_sync(0xffffffffu, v, 1);
            v += __shfl_xor_sync(0xffffffffu, v, 2);
            racc[mt][hf] = v;
        }
    }
    __syncthreads();
    if (c == 0) {
#pragma unroll
        for (int mt = 0; mt < 2; mt++) {
            const int r0 = wm * 32 + mt * 16 + g;
            red[wn][r0] = racc[mt][0];
            red[wn][r0 + 8] = racc[mt][1];
        }
    }
    __syncthreads();
    if (tid < 64) {
        float s = red[0][tid] + red[1][tid] + red[2][tid] + red[3][tid];
        score[((size_t)b * HH + h) * SS + i0 + tid] = SCALING * (s + ba[0]);
    }
}

// ---------------------------------------------------------------------------
// Masked softmax / pooling / head
// ---------------------------------------------------------------------------
__global__ void __launch_bounds__(256) softmax_kernel(float* __restrict__ score,
                                                      const int* __restrict__ mask)
{
    float* row = score + (size_t)blockIdx.x * SS;
    __shared__ float red[256];
    const int tid = threadIdx.x;

    float mx = -3.4e38f;
    for (int i = tid; i < SS; i += 256) {
        float v = (mask[i] != 0) ? NEGV : row[i];
        row[i] = v;
        mx = fmaxf(mx, v);
    }
    red[tid] = mx; __syncthreads();
    for (int o = 128; o >= 1; o >>= 1) {
        if (tid < o) red[tid] = fmaxf(red[tid], red[tid + o]);
        __syncthreads();
    }
    mx = red[0];
    __syncthreads();

    float sum = 0.f;
    for (int i = tid; i < SS; i += 256) {
        float e = __expf(row[i] - mx);
        row[i] = e;
        sum += e;
    }
    red[tid] = sum; __syncthreads();
    for (int o = 128; o >= 1; o >>= 1) {
        if (tid < o) red[tid] += red[tid + o];
        __syncthreads();
    }
    float inv = 1.f / red[0];
    for (int i = tid; i < SS; i += 256) row[i] *= inv;
}

__global__ void __launch_bounds__(256) pool_kernel(
    const __half* __restrict__ V, const float* __restrict__ attn,
    float* __restrict__ pooled)
{
    const int b = blockIdx.z, h = blockIdx.y;
    const int d = threadIdx.x;
    const int i0 = blockIdx.x * 128;
    const __half* Vh = V + (size_t)b * SS * DD + h * DKK + d;
    const float* a = attn + ((size_t)b * HH + h) * SS;
    float acc = 0.f;
#pragma unroll 4
    for (int i = i0; i < i0 + 128; i++)
        acc += a[i] * __half2float(Vh[(size_t)i * DD]);
    atomicAdd(&pooled[(size_t)b * DD + h * DKK + d], acc);
}

// one warp per n; handles BOTH batches (reads Wp row once)
__global__ void __launch_bounds__(256) final_kernel(
    const float* __restrict__ pooled, const float* __restrict__ Wp,
    const float* __restrict__ bp, float* __restrict__ out)
{
    const int warp = (blockIdx.x * blockDim.x + threadIdx.x) >> 5;
    const int lane = threadIdx.x & 31;
    const int n = warp;
    const float* wrow = Wp + (size_t)n * DD;
    const float* p0 = pooled;
    const float* p1 = pooled + DD;
    float a0 = 0.f, a1 = 0.f;
    for (int k = lane * 4; k < DD; k += 128) {
        float4 w = *reinterpret_cast<const float4*>(wrow + k);
        float4 q0 = *reinterpret_cast<const float4*>(p0 + k);
        float4 q1 = *reinterpret_cast<const float4*>(p1 + k);
        a0 += w.x * q0.x + w.y * q0.y + w.z * q0.z + w.w * q0.w;
        a1 += w.x * q1.x + w.y * q1.y + w.z * q1.z + w.w * q1.w;
    }
#pragma unroll
    for (int o = 16; o >= 1; o >>= 1) {
        a0 += __shfl_xor_sync(0xffffffffu, a0, o);
        a1 += __shfl_xor_sync(0xffffffffu, a1, o);
    }
    if (lane == 0) {
        float bb = bp[n];
        out[n] = tanhf(a0 + bb);
        out[DD + n] = tanhf(a1 + bb);
    }
}

extern "C" void kernel_launch(void* const* d_in, const int* in_sizes, int n_in,
                              void* d_out, int out_size)
{
    const float* x    = (const float*)d_in[0];
    const int*   xmsk = (const int*)  d_in[1];
    const float* Wq   = (const float*)d_in[2];
    const float* bq   = (const float*)d_in[3];
    const float* Wk   = (const float*)d_in[4];
    const float* bk   = (const float*)d_in[5];
    const float* Wv   = (const float*)d_in[6];
    const float* bv   = (const float*)d_in[7];
    const float* Wa   = (const float*)d_in[8];
    const float* ba   = (const float*)d_in[9];
    const float* Wp   = (const float*)d_in[10];
    const float* bp   = (const float*)d_in[11];
    float* out = (float*)d_out;

    __half *Xh, *Wh, *Qh, *Kh, *Vh;
    float *Sp, *Pp, *Bp;
    cudaGetSymbolAddress((void**)&Xh, g_xh);
    cudaGetSymbolAddress((void**)&Wh, g_Wh);
    cudaGetSymbolAddress((void**)&Qh, g_Qh);
    cudaGetSymbolAddress((void**)&Kh, g_Kh);
    cudaGetSymbolAddress((void**)&Vh, g_Vh);
    cudaGetSymbolAddress((void**)&Sp, g_score);
    cudaGetSymbolAddress((void**)&Pp, g_pool);
    cudaGetSymbolAddress((void**)&Bp, g_bias);

    static int attr_done = 0;
    if (!attr_done) {
        cudaFuncSetAttribute(gemm_qkv_fused,
                             cudaFuncAttributeMaxDynamicSharedMemorySize, QKV_SMEM);
        cudaFuncSetAttribute(score_f16_kernel,
                             cudaFuncAttributeMaxDynamicSharedMemorySize, SC_SMEM_BYTES);
        attr_done = 1;
    }

    // fused operand conversion + bias packing (+ pool zeroing)
    const int ntot4 = NX4 + 3 * NW4;
    f2h_all_kernel<<<ntot4 / 256, 256>>>(x, Wq, Wk, Wv, Xh, Wh);
    pack_bias_kernel<<<(3 * DD + 255) / 256, 256>>>(bq, bk, bv, Bp, Pp);

    // fused QKV projection: grid (48, 32), 256 threads, BK=64
    dim3 gq(3 * DD / 128, (BB * SS) / 128);
    gemm_qkv_fused<<<gq, 256, QKV_SMEM>>>(Xh, Wh, Bp, Qh, Kh, Vh);

    // score: 64-row i-tiles -> grid (32, 8, 2) = 512 blocks, 2 CTA/SM
    score_f16_kernel<<<dim3(SS / 64, HH, BB), 256, SC_SMEM_BYTES>>>(Qh, Kh, Wa, ba, Sp);
    softmax_kernel<<<BB * HH, 256>>>(Sp, xmsk);

    pool_kernel<<<dim3(SS / 128, HH, BB), 256>>>(Vh, Sp, Pp);
    final_kernel<<<(BB * DD / 2) / 8, 256>>>(Pp, Wp, bp, out);
}

// round 15
// speedup vs baseline: 1.0107x; 1.0107x over previous
#include <cuda_runtime.h>
#include <cuda_fp16.h>
#include <cstdint>

#define BB 2
#define SS 2048
#define DD 2048
#define HH 8
#define DKK 256
#define SCALING 0.0625f
#define NEGV (-1e9f)
#define QSPAD 72      // BK=64 row stride (halves): 144B, ldsm conflict-free
#define QPAD 264      // score persistent-Q row stride (halves)

// Scratch (device globals; no allocation allowed)
__device__ __half g_xh[(size_t)BB * SS * DD];
__device__ __half g_Wh[3][(size_t)DD * DD];   // packed [3*DD][DD]
__device__ float  g_bias[3 * DD];
__device__ __half g_Qh[(size_t)BB * SS * DD];
__device__ __half g_Kh[(size_t)BB * SS * DD];
__device__ __half g_Vh[(size_t)BB * SS * DD];
__device__ float  g_score[BB * HH * SS];
__device__ float  g_pool[BB * DD];

// ---------------------------------------------------------------------------
// helpers
// ---------------------------------------------------------------------------
#define MMA_F16(d0,d1,d2,d3,a0,a1,a2,a3,b0,b1)                                \
    asm volatile("mma.sync.aligned.m16n8k16.row.col.f32.f16.f16.f32 "         \
                 "{%0,%1,%2,%3},{%4,%5,%6,%7},{%8,%9},{%0,%1,%2,%3};"         \
                 : "+f"(d0), "+f"(d1), "+f"(d2), "+f"(d3)                     \
                 : "r"(a0), "r"(a1), "r"(a2), "r"(a3), "r"(b0), "r"(b1))

#define LDSM_X4(r0,r1,r2,r3,addr)                                             \
    asm volatile("ldmatrix.sync.aligned.m8n8.x4.shared.b16 {%0,%1,%2,%3},[%4];" \
                 : "=r"(r0), "=r"(r1), "=r"(r2), "=r"(r3) : "r"(addr))

__device__ __forceinline__ void cp16(void* smem, const void* gmem) {
    uint32_t sa = (uint32_t)__cvta_generic_to_shared(smem);
    asm volatile("cp.async.cg.shared.global [%0], [%1], 16;" :: "r"(sa), "l"(gmem));
}
__device__ __forceinline__ void cp_commit() { asm volatile("cp.async.commit_group;"); }
template<int N> __device__ __forceinline__ void cp_wait() {
    asm volatile("cp.async.wait_group %0;" :: "n"(N));
}
__device__ __forceinline__ uint32_t s2u(const void* p) {
    return (uint32_t)__cvta_generic_to_shared(p);
}

// ---------------------------------------------------------------------------
// Fused f32->f16 convert of x + Wq/Wk/Wv
// ---------------------------------------------------------------------------
#define NX4 (1 << 22)
#define NW4 (1 << 20)

__global__ void __launch_bounds__(256) f2h_all_kernel(
    const float* __restrict__ x,
    const float* __restrict__ w0, const float* __restrict__ w1,
    const float* __restrict__ w2,
    __half* __restrict__ xh, __half* __restrict__ wh)
{
    int i = blockIdx.x * blockDim.x + threadIdx.x;
    const float* in;
    __half* out;
    int off;
    if (i < NX4) {
        in = x; out = xh; off = i;
    } else {
        int j = i - NX4;
        int seg = j >> 20;
        off = j & (NW4 - 1);
        in = (seg == 0) ? w0 : (seg == 1) ? w1 : w2;
        out = wh + (size_t)seg * DD * DD;
    }
    float4 v = reinterpret_cast<const float4*>(in)[off];
    reinterpret_cast<__half2*>(out)[2 * off] = __floats2half2_rn(v.x, v.y);
    reinterpret_cast<__half2*>(out)[2 * off + 1] = __floats2half2_rn(v.z, v.w);
}

// pack biases AND zero the pool accumulator (one launch)
__global__ void pack_bias_kernel(const float* __restrict__ b0,
                                 const float* __restrict__ b1,
                                 const float* __restrict__ b2,
                                 float* __restrict__ out,
                                 float* __restrict__ pool)
{
    int i = blockIdx.x * blockDim.x + threadIdx.x;
    if (i < DD) out[i] = b0[i];
    else if (i < 2 * DD) out[i] = b1[i - DD];
    else if (i < 3 * DD) out[i] = b2[i - 2 * DD];
    if (i < BB * DD) pool[i] = 0.f;
}

// ---------------------------------------------------------------------------
// Fused QKV fp16 NT GEMM (R13, unchanged). CTA 128x128, BK=64, 3-stage,
// 256 threads = 8 warps (2 x 4), warp tile 64x32, 2 CTA/SM.
// ---------------------------------------------------------------------------
#define QKV_SMEM (3 * 2 * 128 * QSPAD * 2)   // 110592 bytes

__global__ void __launch_bounds__(256) gemm_qkv_fused(
    const __half* __restrict__ A, const __half* __restrict__ W,
    const float* __restrict__ bias,
    __half* __restrict__ Qo, __half* __restrict__ Ko, __half* __restrict__ Vo)
{
    extern __shared__ __half smem[];
    __half (*As)[128][QSPAD] = reinterpret_cast<__half(*)[128][QSPAD]>(smem);
    __half (*Bs)[128][QSPAD] = reinterpret_cast<__half(*)[128][QSPAD]>(smem + 3 * 128 * QSPAD);

    const int K = DD;
    const int bm = blockIdx.y * 128;
    const int bn = blockIdx.x * 128;
    const int tid = threadIdx.x;
    const int warp = tid >> 5, lane = tid & 31;
    const int wm = warp & 1, wn = warp >> 1;
    const int g = lane >> 2, c = lane & 3;
    const int lrow = tid >> 3, lc8 = (tid & 7) * 8;

    float acc[4][4][4];
#pragma unroll
    for (int i = 0; i < 4; i++)
#pragma unroll
        for (int j = 0; j < 4; j++)
#pragma unroll
            for (int r = 0; r < 4; r++) acc[i][j][r] = 0.f;

    const int nk = K >> 6;   // 32

#pragma unroll
    for (int s = 0; s < 2; s++) {
        const int k0 = s << 6;
#pragma unroll
        for (int r = 0; r < 128; r += 32) {
            cp16(&As[s][lrow + r][lc8], A + (size_t)(bm + lrow + r) * K + k0 + lc8);
            cp16(&Bs[s][lrow + r][lc8], W + (size_t)(bn + lrow + r) * K + k0 + lc8);
        }
        cp_commit();
    }

    const int a_row = wm * 64 + (lane & 15);
    const int a_koff = (lane >> 4) << 3;
    const int b_row = wn * 32 + (lane & 7) + ((lane >> 4) << 3);
    const int b_koff = ((lane >> 3) & 1) << 3;

    for (int kt = 0; kt < nk; kt++) {
        cp_wait<1>();
        __syncthreads();

        const int pf = kt + 2;
        if (pf < nk) {
            const int pb = pf % 3;
            const int k0 = pf << 6;
#pragma unroll
            for (int r = 0; r < 128; r += 32) {
                cp16(&As[pb][lrow + r][lc8], A + (size_t)(bm + lrow + r) * K + k0 + lc8);
                cp16(&Bs[pb][lrow + r][lc8], W + (size_t)(bn + lrow + r) * K + k0 + lc8);
            }
        }
        cp_commit();

        const int buf = kt % 3;
#pragma unroll
        for (int kk = 0; kk < 4; kk++) {
            const int k = kk * 16;
            uint32_t af[4][4], bf[4][2];
#pragma unroll
            for (int mt = 0; mt < 4; mt++) {
                uint32_t ad = s2u(&As[buf][a_row + mt * 16][k + a_koff]);
                LDSM_X4(af[mt][0], af[mt][1], af[mt][2], af[mt][3], ad);
            }
#pragma unroll
            for (int nt2 = 0; nt2 < 2; nt2++) {
                uint32_t bd = s2u(&Bs[buf][b_row + nt2 * 16][k + b_koff]);
                LDSM_X4(bf[nt2 * 2][0], bf[nt2 * 2][1],
                        bf[nt2 * 2 + 1][0], bf[nt2 * 2 + 1][1], bd);
            }
#pragma unroll
            for (int mt = 0; mt < 4; mt++)
#pragma unroll
                for (int nt = 0; nt < 4; nt++)
                    MMA_F16(acc[mt][nt][0], acc[mt][nt][1], acc[mt][nt][2], acc[mt][nt][3],
                            af[mt][0], af[mt][1], af[mt][2], af[mt][3],
                            bf[nt][0], bf[nt][1]);
        }
    }

    const int seg = bn >> 11;                    // 0=Q 1=K 2=V
    const int nbase = bn & 2047;
    __half* dst = (seg == 0) ? Qo : (seg == 1) ? Ko : Vo;
#pragma unroll
    for (int mt = 0; mt < 4; mt++) {
        const int r = bm + wm * 64 + mt * 16 + g;
#pragma unroll
        for (int nt = 0; nt < 4; nt++) {
            const int gcol = bn + wn * 32 + nt * 8 + 2 * c;
            const int col = nbase + wn * 32 + nt * 8 + 2 * c;
            const float b0 = bias[gcol], b1 = bias[gcol + 1];
            *reinterpret_cast<__half2*>(&dst[(size_t)r * DD + col]) =
                __floats2half2_rn(acc[mt][nt][0] + b0, acc[mt][nt][1] + b1);
            *reinterpret_cast<__half2*>(&dst[(size_t)(r + 8) * DD + col]) =
                __floats2half2_rn(acc[mt][nt][2] + b0, acc[mt][nt][3] + b1);
        }
    }
}

// ---------------------------------------------------------------------------
// fp16 score kernel v3: 128-row i-tile (R13 geometry), Q resident,
// K streamed with BK=64 / 3-stage (half the barriers of the 107us version).
// 8 warps = 2 wm(64 rows) x 4 wn(32 cols).
// score[b,h,i] = SCALING*(sum_j leaky(q_i.k_j)*Wa[j] + ba)
// ---------------------------------------------------------------------------
#define SC_OFF_K (128 * QPAD)                          // halves
#define SC_OFF_RED (SC_OFF_K + 3 * 128 * QSPAD)        // halves
#define SC_SMEM_BYTES ((SC_OFF_RED) * 2 + 4 * 128 * 4) // 124928

__global__ void __launch_bounds__(256) score_f16_kernel(
    const __half* __restrict__ Q, const __half* __restrict__ Kb,
    const float* __restrict__ Wa, const float* __restrict__ ba,
    float* __restrict__ score)
{
    extern __shared__ __half hsmem[];
    __half (*Qs)[QPAD] = reinterpret_cast<__half(*)[QPAD]>(hsmem);
    __half (*Ks)[128][QSPAD] = reinterpret_cast<__half(*)[128][QSPAD]>(hsmem + SC_OFF_K);
    float (*red)[128] = reinterpret_cast<float(*)[128]>(hsmem + SC_OFF_RED);

    const int b = blockIdx.z, h = blockIdx.y;
    const int i0 = blockIdx.x * 128;
    const __half* Qg = Q + (size_t)b * SS * DD + (size_t)h * DKK;
    const __half* Kg = Kb + (size_t)b * SS * DD + (size_t)h * DKK;

    const int tid = threadIdx.x;
    const int warp = tid >> 5, lane = tid & 31;
    const int wm = warp & 1, wn = warp >> 1;
    const int g = lane >> 2, c = lane & 3;
    const int lrow = tid >> 3, lc8 = (tid & 7) * 8;    // K loader: 8 chunks/row

    const int a_row = wm * 64 + (lane & 15);
    const int a_koff = (lane >> 4) << 3;
    const int b_row = wn * 32 + (lane & 7) + ((lane >> 4) << 3);
    const int b_koff = ((lane >> 3) & 1) << 3;

    // one-time Q tile load: 128 rows x 256 halves = 4096 16B chunks
#pragma unroll
    for (int t = 0; t < 16; t++) {
        int chunk = tid + t * 256;
        int row = chunk >> 5, cc = chunk & 31;
        cp16(&Qs[row][cc * 8], Qg + (size_t)(i0 + row) * DD + cc * 8);
    }
    cp_commit();

    float racc[4][2];
#pragma unroll
    for (int mt = 0; mt < 4; mt++) { racc[mt][0] = 0.f; racc[mt][1] = 0.f; }

    const int nk = DKK >> 6;   // 4 k-tiles of 64

    for (int j0 = 0; j0 < SS; j0 += 128) {
        float acc[4][4][4];
#pragma unroll
        for (int i = 0; i < 4; i++)
#pragma unroll
            for (int j = 0; j < 4; j++)
#pragma unroll
                for (int r = 0; r < 4; r++) acc[i][j][r] = 0.f;

        // prologue: stages 0,1 of this j-tile's K
#pragma unroll
        for (int s = 0; s < 2; s++) {
            const int k0 = s << 6;
#pragma unroll
            for (int r = 0; r < 128; r += 32)
                cp16(&Ks[s][lrow + r][lc8], Kg + (size_t)(j0 + lrow + r) * DD + k0 + lc8);
            cp_commit();
        }

        for (int kt = 0; kt < nk; kt++) {
            cp_wait<1>();       // first iter also drains the Q group
            __syncthreads();

            const int pf = kt + 2;
            if (pf < nk) {
                const int pb = pf % 3;
                const int k0 = pf << 6;
#pragma unroll
                for (int r = 0; r < 128; r += 32)
                    cp16(&Ks[pb][lrow + r][lc8], Kg + (size_t)(j0 + lrow + r) * DD + k0 + lc8);
            }
            cp_commit();

            const int buf = kt % 3;
            const int kg = kt << 6;      // Q's global k offset
#pragma unroll
            for (int kk = 0; kk < 4; kk++) {
                const int k = kk * 16;
                uint32_t af[4][4], bf[4][2];
#pragma unroll
                for (int mt = 0; mt < 4; mt++) {
                    uint32_t ad = s2u(&Qs[a_row + mt * 16][kg + k + a_koff]);
                    LDSM_X4(af[mt][0], af[mt][1], af[mt][2], af[mt][3], ad);
                }
#pragma unroll
                for (int nt2 = 0; nt2 < 2; nt2++) {
                    uint32_t bd = s2u(&Ks[buf][b_row + nt2 * 16][k + b_koff]);
                    LDSM_X4(bf[nt2 * 2][0], bf[nt2 * 2][1],
                            bf[nt2 * 2 + 1][0], bf[nt2 * 2 + 1][1], bd);
                }
#pragma unroll
                for (int mt = 0; mt < 4; mt++)
#pragma unroll
                    for (int nt = 0; nt < 4; nt++)
                        MMA_F16(acc[mt][nt][0], acc[mt][nt][1], acc[mt][nt][2], acc[mt][nt][3],
                                af[mt][0], af[mt][1], af[mt][2], af[mt][3],
                                bf[nt][0], bf[nt][1]);
            }
        }
        __syncthreads();   // protect K stages from next j-tile prologue

        // fused epilogue: leaky_relu -> * Wa[j] -> fold into per-row accumulator
#pragma unroll
        for (int nt = 0; nt < 4; nt++) {
            const int colg = j0 + wn * 32 + nt * 8 + 2 * c;
            const float wa0 = Wa[colg], wa1 = Wa[colg + 1];
#pragma unroll
            for (int mt = 0; mt < 4; mt++) {
                float e0 = acc[mt][nt][0]; e0 = (e0 >= 0.f) ? e0 : 0.1f * e0;
                float e1 = acc[mt][nt][1]; e1 = (e1 >= 0.f) ? e1 : 0.1f * e1;
                float e2 = acc[mt][nt][2]; e2 = (e2 >= 0.f) ? e2 : 0.1f * e2;
                float e3 = acc[mt][nt][3]; e3 = (e3 >= 0.f) ? e3 : 0.1f * e3;
                racc[mt][0] += e0 * wa0 + e1 * wa1;
                racc[mt][1] += e2 * wa0 + e3 * wa1;
            }
        }
    }

    // reduce across the 4 "c" lanes of each quad
#pragma unroll
    for (int mt = 0; mt < 4; mt++) {
#pragma unroll
        for (int hf = 0; hf < 2; hf++) {
            float v = racc[mt][hf];
            v += __shfl_xor_sync(0xffffffffu, v, 1);
            v += __shfl_xor_sync(0xffffffffu, v, 2);
            racc[mt][hf] = v;
        }
    }
    __syncthreads();
    if (c == 0) {
#pragma unroll
        for (int mt = 0; mt < 4; mt++) {
            const int r0 = wm * 64 + mt * 16 + g;
            red[wn][r0] = racc[mt][0];
            red[wn][r0 + 8] = racc[mt][1];
        }
    }
    __syncthreads();
    if (tid < 128) {
        float s = red[0][tid] + red[1][tid] + red[2][tid] + red[3][tid];
        score[((size_t)b * HH + h) * SS + i0 + tid] = SCALING * (s + ba[0]);
    }
}

// ---------------------------------------------------------------------------
// Masked softmax / pooling / head
// ---------------------------------------------------------------------------
__global__ void __launch_bounds__(256) softmax_kernel(float* __restrict__ score,
                                                      const int* __restrict__ mask)
{
    float* row = score + (size_t)blockIdx.x * SS;
    __shared__ float red[256];
    const int tid = threadIdx.x;

    float mx = -3.4e38f;
    for (int i = tid; i < SS; i += 256) {
        float v = (mask[i] != 0) ? NEGV : row[i];
        row[i] = v;
        mx = fmaxf(mx, v);
    }
    red[tid] = mx; __syncthreads();
    for (int o = 128; o >= 1; o >>= 1) {
        if (tid < o) red[tid] = fmaxf(red[tid], red[tid + o]);
        __syncthreads();
    }
    mx = red[0];
    __syncthreads();

    float sum = 0.f;
    for (int i = tid; i < SS; i += 256) {
        float e = __expf(row[i] - mx);
        row[i] = e;
        sum += e;
    }
    red[tid] = sum; __syncthreads();
    for (int o = 128; o >= 1; o >>= 1) {
        if (tid < o) red[tid] += red[tid + o];
        __syncthreads();
    }
    float inv = 1.f / red[0];
    for (int i = tid; i < SS; i += 256) row[i] *= inv;
}

__global__ void __launch_bounds__(256) pool_kernel(
    const __half* __restrict__ V, const float* __restrict__ attn,
    float* __restrict__ pooled)
{
    const int b = blockIdx.z, h = blockIdx.y;
    const int d = threadIdx.x;
    const int i0 = blockIdx.x * 128;
    const __half* Vh = V + (size_t)b * SS * DD + h * DKK + d;
    const float* a = attn + ((size_t)b * HH + h) * SS;
    float acc = 0.f;
#pragma unroll 4
    for (int i = i0; i < i0 + 128; i++)
        acc += a[i] * __half2float(Vh[(size_t)i * DD]);
    atomicAdd(&pooled[(size_t)b * DD + h * DKK + d], acc);
}

// one warp per n; handles BOTH batches (reads Wp row once)
__global__ void __launch_bounds__(256) final_kernel(
    const float* __restrict__ pooled, const float* __restrict__ Wp,
    const float* __restrict__ bp, float* __restrict__ out)
{
    const int warp = (blockIdx.x * blockDim.x + threadIdx.x) >> 5;
    const int lane = threadIdx.x & 31;
    const int n = warp;
    const float* wrow = Wp + (size_t)n * DD;
    const float* p0 = pooled;
    const float* p1 = pooled + DD;
    float a0 = 0.f, a1 = 0.f;
    for (int k = lane * 4; k < DD; k += 128) {
        float4 w = *reinterpret_cast<const float4*>(wrow + k);
        float4 q0 = *reinterpret_cast<const float4*>(p0 + k);
        float4 q1 = *reinterpret_cast<const float4*>(p1 + k);
        a0 += w.x * q0.x + w.y * q0.y + w.z * q0.z + w.w * q0.w;
        a1 += w.x * q1.x + w.y * q1.y + w.z * q1.z + w.w * q1.w;
    }
#pragma unroll
    for (int o = 16; o >= 1; o >>= 1) {
        a0 += __shfl_xor_sync(0xffffffffu, a0, o);
        a1 += __shfl_xor_sync(0xffffffffu, a1, o);
    }
    if (lane == 0) {
        float bb = bp[n];
        out[n] = tanhf(a0 + bb);
        out[DD + n] = tanhf(a1 + bb);
    }
}

extern "C" void kernel_launch(void* const* d_in, const int* in_sizes, int n_in,
                              void* d_out, int out_size)
{
    const float* x    = (const float*)d_in[0];
    const int*   xmsk = (const int*)  d_in[1];
    const float* Wq   = (const float*)d_in[2];
    const float* bq   = (const float*)d_in[3];
    const float* Wk   = (const float*)d_in[4];
    const float* bk   = (const float*)d_in[5];
    const float* Wv   = (const float*)d_in[6];
    const float* bv   = (const float*)d_in[7];
    const float* Wa   = (const float*)d_in[8];
    const float* ba   = (const float*)d_in[9];
    const float* Wp   = (const float*)d_in[10];
    const float* bp   = (const float*)d_in[11];
    float* out = (float*)d_out;

    __half *Xh, *Wh, *Qh, *Kh, *Vh;
    float *Sp, *Pp, *Bp;
    cudaGetSymbolAddress((void**)&Xh, g_xh);
    cudaGetSymbolAddress((void**)&Wh, g_Wh);
    cudaGetSymbolAddress((void**)&Qh, g_Qh);
    cudaGetSymbolAddress((void**)&Kh, g_Kh);
    cudaGetSymbolAddress((void**)&Vh, g_Vh);
    cudaGetSymbolAddress((void**)&Sp, g_score);
    cudaGetSymbolAddress((void**)&Pp, g_pool);
    cudaGetSymbolAddress((void**)&Bp, g_bias);

    static int attr_done = 0;
    if (!attr_done) {
        cudaFuncSetAttribute(gemm_qkv_fused,
                             cudaFuncAttributeMaxDynamicSharedMemorySize, QKV_SMEM);
        cudaFuncSetAttribute(score_f16_kernel,
                             cudaFuncAttributeMaxDynamicSharedMemorySize, SC_SMEM_BYTES);
        attr_done = 1;
    }

    // fused operand conversion + bias packing (+ pool zeroing)
    const int ntot4 = NX4 + 3 * NW4;
    f2h_all_kernel<<<ntot4 / 256, 256>>>(x, Wq, Wk, Wv, Xh, Wh);
    pack_bias_kernel<<<(3 * DD + 255) / 256, 256>>>(bq, bk, bv, Bp, Pp);

    // fused QKV projection: grid (48, 32), 256 threads, BK=64
    dim3 gq(3 * DD / 128, (BB * SS) / 128);
    gemm_qkv_fused<<<gq, 256, QKV_SMEM>>>(Xh, Wh, Bp, Qh, Kh, Vh);

    // score: 128-row i-tiles (R13 geometry), BK=64 K streaming
    score_f16_kernel<<<dim3(SS / 128, HH, BB), 256, SC_SMEM_BYTES>>>(Qh, Kh, Wa, ba, Sp);
    softmax_kernel<<<BB * HH, 256>>>(Sp, xmsk);

    pool_kernel<<<dim3(SS / 128, HH, BB), 256>>>(Vh, Sp, Pp);
    final_kernel<<<(BB * DD / 2) / 8, 256>>>(Pp, Wp, bp, out);
}

// round 16
// speedup vs baseline: 1.0640x; 1.0527x over previous
#include <cuda_runtime.h>
#include <cuda_fp16.h>
#include <cstdint>

#define BB 2
#define SS 2048
#define DD 2048
#define HH 8
#define DKK 256
#define SCALING 0.0625f
#define NEGV (-1e9f)
#define QSPAD 72      // BK=64 row stride (halves): 144B, ldsm conflict-free
#define QPAD 264      // score persistent-Q row stride (halves)

// Scratch (device globals; no allocation allowed)
__device__ __half g_xh[(size_t)BB * SS * DD];
__device__ __half g_Wh[3][(size_t)DD * DD];   // packed [3*DD][DD]
__device__ float  g_bias[3 * DD];
__device__ __half g_Qh[(size_t)BB * SS * DD];
__device__ __half g_Kh[(size_t)BB * SS * DD];
__device__ __half g_Vh[(size_t)BB * SS * DD];
__device__ float  g_score[BB * HH * SS];
__device__ float  g_pool[BB * DD];

// ---------------------------------------------------------------------------
// helpers
// ---------------------------------------------------------------------------
#define MMA_F16(d0,d1,d2,d3,a0,a1,a2,a3,b0,b1)                                \
    asm volatile("mma.sync.aligned.m16n8k16.row.col.f32.f16.f16.f32 "         \
                 "{%0,%1,%2,%3},{%4,%5,%6,%7},{%8,%9},{%0,%1,%2,%3};"         \
                 : "+f"(d0), "+f"(d1), "+f"(d2), "+f"(d3)                     \
                 : "r"(a0), "r"(a1), "r"(a2), "r"(a3), "r"(b0), "r"(b1))

#define LDSM_X4(r0,r1,r2,r3,addr)                                             \
    asm volatile("ldmatrix.sync.aligned.m8n8.x4.shared.b16 {%0,%1,%2,%3},[%4];" \
                 : "=r"(r0), "=r"(r1), "=r"(r2), "=r"(r3) : "r"(addr))

__device__ __forceinline__ void cp16(void* smem, const void* gmem) {
    uint32_t sa = (uint32_t)__cvta_generic_to_shared(smem);
    asm volatile("cp.async.cg.shared.global [%0], [%1], 16;" :: "r"(sa), "l"(gmem));
}
__device__ __forceinline__ void cp_commit() { asm volatile("cp.async.commit_group;"); }
template<int N> __device__ __forceinline__ void cp_wait() {
    asm volatile("cp.async.wait_group %0;" :: "n"(N));
}
__device__ __forceinline__ uint32_t s2u(const void* p) {
    return (uint32_t)__cvta_generic_to_shared(p);
}

// ---------------------------------------------------------------------------
// Fused f32->f16 convert of x + Wq/Wk/Wv
// ---------------------------------------------------------------------------
#define NX4 (1 << 22)
#define NW4 (1 << 20)

__global__ void __launch_bounds__(256) f2h_all_kernel(
    const float* __restrict__ x,
    const float* __restrict__ w0, const float* __restrict__ w1,
    const float* __restrict__ w2,
    __half* __restrict__ xh, __half* __restrict__ wh)
{
    int i = blockIdx.x * blockDim.x + threadIdx.x;
    const float* in;
    __half* out;
    int off;
    if (i < NX4) {
        in = x; out = xh; off = i;
    } else {
        int j = i - NX4;
        int seg = j >> 20;
        off = j & (NW4 - 1);
        in = (seg == 0) ? w0 : (seg == 1) ? w1 : w2;
        out = wh + (size_t)seg * DD * DD;
    }
    float4 v = reinterpret_cast<const float4*>(in)[off];
    reinterpret_cast<__half2*>(out)[2 * off] = __floats2half2_rn(v.x, v.y);
    reinterpret_cast<__half2*>(out)[2 * off + 1] = __floats2half2_rn(v.z, v.w);
}

// pack biases AND zero the pool accumulator (one launch)
__global__ void pack_bias_kernel(const float* __restrict__ b0,
                                 const float* __restrict__ b1,
                                 const float* __restrict__ b2,
                                 float* __restrict__ out,
                                 float* __restrict__ pool)
{
    int i = blockIdx.x * blockDim.x + threadIdx.x;
    if (i < DD) out[i] = b0[i];
    else if (i < 2 * DD) out[i] = b1[i - DD];
    else if (i < 3 * DD) out[i] = b2[i - 2 * DD];
    if (i < BB * DD) pool[i] = 0.f;
}

// ---------------------------------------------------------------------------
// Fused QKV fp16 NT GEMM (R13, unchanged). CTA 128x128, BK=64, 3-stage,
// 256 threads = 8 warps (2 x 4), warp tile 64x32, 2 CTA/SM.
// ---------------------------------------------------------------------------
#define QKV_SMEM (3 * 2 * 128 * QSPAD * 2)   // 110592 bytes

__global__ void __launch_bounds__(256) gemm_qkv_fused(
    const __half* __restrict__ A, const __half* __restrict__ W,
    const float* __restrict__ bias,
    __half* __restrict__ Qo, __half* __restrict__ Ko, __half* __restrict__ Vo)
{
    extern __shared__ __half smem[];
    __half (*As)[128][QSPAD] = reinterpret_cast<__half(*)[128][QSPAD]>(smem);
    __half (*Bs)[128][QSPAD] = reinterpret_cast<__half(*)[128][QSPAD]>(smem + 3 * 128 * QSPAD);

    const int K = DD;
    const int bm = blockIdx.y * 128;
    const int bn = blockIdx.x * 128;
    const int tid = threadIdx.x;
    const int warp = tid >> 5, lane = tid & 31;
    const int wm = warp & 1, wn = warp >> 1;
    const int g = lane >> 2, c = lane & 3;
    const int lrow = tid >> 3, lc8 = (tid & 7) * 8;

    float acc[4][4][4];
#pragma unroll
    for (int i = 0; i < 4; i++)
#pragma unroll
        for (int j = 0; j < 4; j++)
#pragma unroll
            for (int r = 0; r < 4; r++) acc[i][j][r] = 0.f;

    const int nk = K >> 6;   // 32

#pragma unroll
    for (int s = 0; s < 2; s++) {
        const int k0 = s << 6;
#pragma unroll
        for (int r = 0; r < 128; r += 32) {
            cp16(&As[s][lrow + r][lc8], A + (size_t)(bm + lrow + r) * K + k0 + lc8);
            cp16(&Bs[s][lrow + r][lc8], W + (size_t)(bn + lrow + r) * K + k0 + lc8);
        }
        cp_commit();
    }

    const int a_row = wm * 64 + (lane & 15);
    const int a_koff = (lane >> 4) << 3;
    const int b_row = wn * 32 + (lane & 7) + ((lane >> 4) << 3);
    const int b_koff = ((lane >> 3) & 1) << 3;

    for (int kt = 0; kt < nk; kt++) {
        cp_wait<1>();
        __syncthreads();

        const int pf = kt + 2;
        if (pf < nk) {
            const int pb = pf % 3;
            const int k0 = pf << 6;
#pragma unroll
            for (int r = 0; r < 128; r += 32) {
                cp16(&As[pb][lrow + r][lc8], A + (size_t)(bm + lrow + r) * K + k0 + lc8);
                cp16(&Bs[pb][lrow + r][lc8], W + (size_t)(bn + lrow + r) * K + k0 + lc8);
            }
        }
        cp_commit();

        const int buf = kt % 3;
#pragma unroll
        for (int kk = 0; kk < 4; kk++) {
            const int k = kk * 16;
            uint32_t af[4][4], bf[4][2];
#pragma unroll
            for (int mt = 0; mt < 4; mt++) {
                uint32_t ad = s2u(&As[buf][a_row + mt * 16][k + a_koff]);
                LDSM_X4(af[mt][0], af[mt][1], af[mt][2], af[mt][3], ad);
            }
#pragma unroll
            for (int nt2 = 0; nt2 < 2; nt2++) {
                uint32_t bd = s2u(&Bs[buf][b_row + nt2 * 16][k + b_koff]);
                LDSM_X4(bf[nt2 * 2][0], bf[nt2 * 2][1],
                        bf[nt2 * 2 + 1][0], bf[nt2 * 2 + 1][1], bd);
            }
#pragma unroll
            for (int mt = 0; mt < 4; mt++)
#pragma unroll
                for (int nt = 0; nt < 4; nt++)
                    MMA_F16(acc[mt][nt][0], acc[mt][nt][1], acc[mt][nt][2], acc[mt][nt][3],
                            af[mt][0], af[mt][1], af[mt][2], af[mt][3],
                            bf[nt][0], bf[nt][1]);
        }
    }

    const int seg = bn >> 11;                    // 0=Q 1=K 2=V
    const int nbase = bn & 2047;
    __half* dst = (seg == 0) ? Qo : (seg == 1) ? Ko : Vo;
#pragma unroll
    for (int mt = 0; mt < 4; mt++) {
        const int r = bm + wm * 64 + mt * 16 + g;
#pragma unroll
        for (int nt = 0; nt < 4; nt++) {
            const int gcol = bn + wn * 32 + nt * 8 + 2 * c;
            const int col = nbase + wn * 32 + nt * 8 + 2 * c;
            const float b0 = bias[gcol], b1 = bias[gcol + 1];
            *reinterpret_cast<__half2*>(&dst[(size_t)r * DD + col]) =
                __floats2half2_rn(acc[mt][nt][0] + b0, acc[mt][nt][1] + b1);
            *reinterpret_cast<__half2*>(&dst[(size_t)(r + 8) * DD + col]) =
                __floats2half2_rn(acc[mt][nt][2] + b0, acc[mt][nt][3] + b1);
        }
    }
}

// ---------------------------------------------------------------------------
// fp16 score kernel v4: 128-row i-tile, Q resident, K 2-stage BK=64 double
// buffer with safe ordering (wait<0> -> sync -> prefetch(other) -> compute).
// smem 106.5 KB -> 2 CTA/SM. 4 barriers per j-tile (vs 9 in the 107us v1).
// score[b,h,i] = SCALING*(sum_j leaky(q_i.k_j)*Wa[j] + ba)
// ---------------------------------------------------------------------------
#define SC_OFF_K (128 * QPAD)                          // 33792 halves
#define SC_OFF_RED (SC_OFF_K + 2 * 128 * QSPAD)        // 52224 halves
#define SC_SMEM_BYTES ((SC_OFF_RED) * 2 + 4 * 128 * 4) // 106496

__global__ void __launch_bounds__(256) score_f16_kernel(
    const __half* __restrict__ Q, const __half* __restrict__ Kb,
    const float* __restrict__ Wa, const float* __restrict__ ba,
    float* __restrict__ score)
{
    extern __shared__ __half hsmem[];
    __half (*Qs)[QPAD] = reinterpret_cast<__half(*)[QPAD]>(hsmem);
    __half (*Ks)[128][QSPAD] = reinterpret_cast<__half(*)[128][QSPAD]>(hsmem + SC_OFF_K);
    float (*red)[128] = reinterpret_cast<float(*)[128]>(hsmem + SC_OFF_RED);

    const int b = blockIdx.z, h = blockIdx.y;
    const int i0 = blockIdx.x * 128;
    const __half* Qg = Q + (size_t)b * SS * DD + (size_t)h * DKK;
    const __half* Kg = Kb + (size_t)b * SS * DD + (size_t)h * DKK;

    const int tid = threadIdx.x;
    const int warp = tid >> 5, lane = tid & 31;
    const int wm = warp & 1, wn = warp >> 1;
    const int g = lane >> 2, c = lane & 3;
    const int lrow = tid >> 3, lc8 = (tid & 7) * 8;    // K loader: 8 chunks/row

    const int a_row = wm * 64 + (lane & 15);
    const int a_koff = (lane >> 4) << 3;
    const int b_row = wn * 32 + (lane & 7) + ((lane >> 4) << 3);
    const int b_koff = ((lane >> 3) & 1) << 3;

    // one-time Q tile load: 128 rows x 256 halves = 4096 16B chunks
#pragma unroll
    for (int t = 0; t < 16; t++) {
        int chunk = tid + t * 256;
        int row = chunk >> 5, cc = chunk & 31;
        cp16(&Qs[row][cc * 8], Qg + (size_t)(i0 + row) * DD + cc * 8);
    }
    cp_commit();

    float racc[4][2];
#pragma unroll
    for (int mt = 0; mt < 4; mt++) { racc[mt][0] = 0.f; racc[mt][1] = 0.f; }

    const int nk = DKK >> 6;   // 4 k-tiles of 64

    for (int j0 = 0; j0 < SS; j0 += 128) {
        float acc[4][4][4];
#pragma unroll
        for (int i = 0; i < 4; i++)
#pragma unroll
            for (int j = 0; j < 4; j++)
#pragma unroll
                for (int r = 0; r < 4; r++) acc[i][j][r] = 0.f;

        // prologue: fill buffer 0 with k-chunk 0
#pragma unroll
        for (int r = 0; r < 128; r += 32)
            cp16(&Ks[0][lrow + r][lc8], Kg + (size_t)(j0 + lrow + r) * DD + lc8);
        cp_commit();

        for (int kt = 0; kt < nk; kt++) {
            // all outstanding loads (incl. prefetch issued at kt-1) complete;
            // sync also guarantees every warp is done computing on the buffer
            // the upcoming prefetch will overwrite.
            cp_wait<0>();
            __syncthreads();

            if (kt + 1 < nk) {
                const int pb = (kt + 1) & 1;
                const int k0 = (kt + 1) << 6;
#pragma unroll
                for (int r = 0; r < 128; r += 32)
                    cp16(&Ks[pb][lrow + r][lc8],
                         Kg + (size_t)(j0 + lrow + r) * DD + k0 + lc8);
                cp_commit();
            }

            const int buf = kt & 1;
            const int kg = kt << 6;      // Q's global k offset
#pragma unroll
            for (int kk = 0; kk < 4; kk++) {
                const int k = kk * 16;
                uint32_t af[4][4], bf[4][2];
#pragma unroll
                for (int mt = 0; mt < 4; mt++) {
                    uint32_t ad = s2u(&Qs[a_row + mt * 16][kg + k + a_koff]);
                    LDSM_X4(af[mt][0], af[mt][1], af[mt][2], af[mt][3], ad);
                }
#pragma unroll
                for (int nt2 = 0; nt2 < 2; nt2++) {
                    uint32_t bd = s2u(&Ks[buf][b_row + nt2 * 16][k + b_koff]);
                    LDSM_X4(bf[nt2 * 2][0], bf[nt2 * 2][1],
                            bf[nt2 * 2 + 1][0], bf[nt2 * 2 + 1][1], bd);
                }
#pragma unroll
                for (int mt = 0; mt < 4; mt++)
#pragma unroll
                    for (int nt = 0; nt < 4; nt++)
                        MMA_F16(acc[mt][nt][0], acc[mt][nt][1], acc[mt][nt][2], acc[mt][nt][3],
                                af[mt][0], af[mt][1], af[mt][2], af[mt][3],
                                bf[nt][0], bf[nt][1]);
            }
        }
        // NOTE: next j-tile's prologue writes Ks[0], last read at kt=nk-2;
        // the sync at kt=nk-1 already ordered all warps past that compute.

        // fused epilogue: leaky_relu -> * Wa[j] -> fold into per-row accumulator
#pragma unroll
        for (int nt = 0; nt < 4; nt++) {
            const int colg = j0 + wn * 32 + nt * 8 + 2 * c;
            const float wa0 = Wa[colg], wa1 = Wa[colg + 1];
#pragma unroll
            for (int mt = 0; mt < 4; mt++) {
                float e0 = acc[mt][nt][0]; e0 = (e0 >= 0.f) ? e0 : 0.1f * e0;
                float e1 = acc[mt][nt][1]; e1 = (e1 >= 0.f) ? e1 : 0.1f * e1;
                float e2 = acc[mt][nt][2]; e2 = (e2 >= 0.f) ? e2 : 0.1f * e2;
                float e3 = acc[mt][nt][3]; e3 = (e3 >= 0.f) ? e3 : 0.1f * e3;
                racc[mt][0] += e0 * wa0 + e1 * wa1;
                racc[mt][1] += e2 * wa0 + e3 * wa1;
            }
        }
    }

    // reduce across the 4 "c" lanes of each quad
#pragma unroll
    for (int mt = 0; mt < 4; mt++) {
#pragma unroll
        for (int hf = 0; hf < 2; hf++) {
            float v = racc[mt][hf];
            v += __shfl_xor_sync(0xffffffffu, v, 1);
            v += __shfl_xor_sync(0xffffffffu, v, 2);
            racc[mt][hf] = v;
        }
    }
    __syncthreads();
    if (c == 0) {
#pragma unroll
        for (int mt = 0; mt < 4; mt++) {
            const int r0 = wm * 64 + mt * 16 + g;
            red[wn][r0] = racc[mt][0];
            red[wn][r0 + 8] = racc[mt][1];
        }
    }
    __syncthreads();
    if (tid < 128) {
        float s = red[0][tid] + red[1][tid] + red[2][tid] + red[3][tid];
        score[((size_t)b * HH + h) * SS + i0 + tid] = SCALING * (s + ba[0]);
    }
}

// ---------------------------------------------------------------------------
// Masked softmax / pooling / head
// ---------------------------------------------------------------------------
__global__ void __launch_bounds__(256) softmax_kernel(float* __restrict__ score,
                                                      const int* __restrict__ mask)
{
    float* row = score + (size_t)blockIdx.x * SS;
    __shared__ float red[256];
    const int tid = threadIdx.x;

    float mx = -3.4e38f;
    for (int i = tid; i < SS; i += 256) {
        float v = (mask[i] != 0) ? NEGV : row[i];
        row[i] = v;
        mx = fmaxf(mx, v);
    }
    red[tid] = mx; __syncthreads();
    for (int o = 128; o >= 1; o >>= 1) {
        if (tid < o) red[tid] = fmaxf(red[tid], red[tid + o]);
        __syncthreads();
    }
    mx = red[0];
    __syncthreads();

    float sum = 0.f;
    for (int i = tid; i < SS; i += 256) {
        float e = __expf(row[i] - mx);
        row[i] = e;
        sum += e;
    }
    red[tid] = sum; __syncthreads();
    for (int o = 128; o >= 1; o >>= 1) {
        if (tid < o) red[tid] += red[tid + o];
        __syncthreads();
    }
    float inv = 1.f / red[0];
    for (int i = tid; i < SS; i += 256) row[i] *= inv;
}

__global__ void __launch_bounds__(256) pool_kernel(
    const __half* __restrict__ V, const float* __restrict__ attn,
    float* __restrict__ pooled)
{
    const int b = blockIdx.z, h = blockIdx.y;
    const int d = threadIdx.x;
    const int i0 = blockIdx.x * 128;
    const __half* Vh = V + (size_t)b * SS * DD + h * DKK + d;
    const float* a = attn + ((size_t)b * HH + h) * SS;
    float acc = 0.f;
#pragma unroll 4
    for (int i = i0; i < i0 + 128; i++)
        acc += a[i] * __half2float(Vh[(size_t)i * DD]);
    atomicAdd(&pooled[(size_t)b * DD + h * DKK + d], acc);
}

// one warp per n; handles BOTH batches (reads Wp row once)
__global__ void __launch_bounds__(256) final_kernel(
    const float* __restrict__ pooled, const float* __restrict__ Wp,
    const float* __restrict__ bp, float* __restrict__ out)
{
    const int warp = (blockIdx.x * blockDim.x + threadIdx.x) >> 5;
    const int lane = threadIdx.x & 31;
    const int n = warp;
    const float* wrow = Wp + (size_t)n * DD;
    const float* p0 = pooled;
    const float* p1 = pooled + DD;
    float a0 = 0.f, a1 = 0.f;
    for (int k = lane * 4; k < DD; k += 128) {
        float4 w = *reinterpret_cast<const float4*>(wrow + k);
        float4 q0 = *reinterpret_cast<const float4*>(p0 + k);
        float4 q1 = *reinterpret_cast<const float4*>(p1 + k);
        a0 += w.x * q0.x + w.y * q0.y + w.z * q0.z + w.w * q0.w;
        a1 += w.x * q1.x + w.y * q1.y + w.z * q1.z + w.w * q1.w;
    }
#pragma unroll
    for (int o = 16; o >= 1; o >>= 1) {
        a0 += __shfl_xor_sync(0xffffffffu, a0, o);
        a1 += __shfl_xor_sync(0xffffffffu, a1, o);
    }
    if (lane == 0) {
        float bb = bp[n];
        out[n] = tanhf(a0 + bb);
        out[DD + n] = tanhf(a1 + bb);
    }
}

extern "C" void kernel_launch(void* const* d_in, const int* in_sizes, int n_in,
                              void* d_out, int out_size)
{
    const float* x    = (const float*)d_in[0];
    const int*   xmsk = (const int*)  d_in[1];
    const float* Wq   = (const float*)d_in[2];
    const float* bq   = (const float*)d_in[3];
    const float* Wk   = (const float*)d_in[4];
    const float* bk   = (const float*)d_in[5];
    const float* Wv   = (const float*)d_in[6];
    const float* bv   = (const float*)d_in[7];
    const float* Wa   = (const float*)d_in[8];
    const float* ba   = (const float*)d_in[9];
    const float* Wp   = (const float*)d_in[10];
    const float* bp   = (const float*)d_in[11];
    float* out = (float*)d_out;

    __half *Xh, *Wh, *Qh, *Kh, *Vh;
    float *Sp, *Pp, *Bp;
    cudaGetSymbolAddress((void**)&Xh, g_xh);
    cudaGetSymbolAddress((void**)&Wh, g_Wh);
    cudaGetSymbolAddress((void**)&Qh, g_Qh);
    cudaGetSymbolAddress((void**)&Kh, g_Kh);
    cudaGetSymbolAddress((void**)&Vh, g_Vh);
    cudaGetSymbolAddress((void**)&Sp, g_score);
    cudaGetSymbolAddress((void**)&Pp, g_pool);
    cudaGetSymbolAddress((void**)&Bp, g_bias);

    static int attr_done = 0;
    if (!attr_done) {
        cudaFuncSetAttribute(gemm_qkv_fused,
                             cudaFuncAttributeMaxDynamicSharedMemorySize, QKV_SMEM);
        cudaFuncSetAttribute(score_f16_kernel,
                             cudaFuncAttributeMaxDynamicSharedMemorySize, SC_SMEM_BYTES);
        attr_done = 1;
    }

    // fused operand conversion + bias packing (+ pool zeroing)
    const int ntot4 = NX4 + 3 * NW4;
    f2h_all_kernel<<<ntot4 / 256, 256>>>(x, Wq, Wk, Wv, Xh, Wh);
    pack_bias_kernel<<<(3 * DD + 255) / 256, 256>>>(bq, bk, bv, Bp, Pp);

    // fused QKV projection: grid (48, 32), 256 threads, BK=64
    dim3 gq(3 * DD / 128, (BB * SS) / 128);
    gemm_qkv_fused<<<gq, 256, QKV_SMEM>>>(Xh, Wh, Bp, Qh, Kh, Vh);

    // score: 128-row i-tiles, BK=64 2-stage, 2 CTA/SM
    score_f16_kernel<<<dim3(SS / 128, HH, BB), 256, SC_SMEM_BYTES>>>(Qh, Kh, Wa, ba, Sp);
    softmax_kernel<<<BB * HH, 256>>>(Sp, xmsk);

    pool_kernel<<<dim3(SS / 128, HH, BB), 256>>>(Vh, Sp, Pp);
    final_kernel<<<(BB * DD / 2) / 8, 256>>>(Pp, Wp, bp, out);
}